// round 15
// baseline (speedup 1.0000x reference)
#include <cuda_runtime.h>
#include <cuda_fp16.h>
#include <math.h>
#include <stdint.h>

// Problem constants
#define Nn   8192
#define Ee   32768
#define DINc 1024
#define DHc  256
#define HHc  8
#define LLc  3
#define HDc  2048   // H*DH
#define NTc  5
#define N2c  4096   // merged Wl|Wr output width
#define EGc  8      // nodes per edge-kernel block

// ---------------- device scratch ----------------
__device__ __half g_xlr[(size_t)Nn * N2c];
__device__ float g_table[LLc * NTc * HDc];
__device__ int   g_deg[Nn];
__device__ int   g_hist[Nn * NTc];
__device__ int   g_rowptr[Nn + 1];
__device__ int   g_woff[Nn];
__device__ int   g_spt[Ee];

__device__ __half g_Apack[(size_t)Nn * DINc];
__device__ __half g_hpack[(size_t)Nn * 2 * DHc];
__device__ __half g_Bpack[4000000];

#define OFF_WIN  0
#define SZ_WIN   (DHc * DINc)
#define SZ_L     ((size_t)N2c * DHc)
#define OFF_WLR(l) (SZ_WIN + (size_t)(l) * SZ_L)
#define OFF_WOUT (SZ_WIN + (size_t)3 * SZ_L)

// ---------------- PTX helpers ----------------
__device__ __forceinline__ uint32_t smem_u32(const void* p) {
    uint32_t a;
    asm("{ .reg .u64 t; cvta.to.shared.u64 t, %1; cvt.u32.u64 %0, t; }" : "=r"(a) : "l"(p));
    return a;
}
__device__ __forceinline__ void cp16(uint32_t d, const void* g) {
    asm volatile("cp.async.cg.shared.global [%0], [%1], 16;" :: "r"(d), "l"(g));
}
__device__ __forceinline__ void ldsm_x4(uint32_t* r, uint32_t addr) {
    asm volatile("ldmatrix.sync.aligned.m8n8.x4.shared.b16 {%0,%1,%2,%3}, [%4];"
                 : "=r"(r[0]), "=r"(r[1]), "=r"(r[2]), "=r"(r[3]) : "r"(addr));
}
__device__ __forceinline__ void mma_f16(float* c, const uint32_t* a, uint32_t b0, uint32_t b1) {
    asm volatile(
        "mma.sync.aligned.m16n8k16.row.col.f32.f16.f16.f32 "
        "{%0,%1,%2,%3}, {%4,%5,%6,%7}, {%8,%9}, {%0,%1,%2,%3};"
        : "+f"(c[0]), "+f"(c[1]), "+f"(c[2]), "+f"(c[3])
        : "r"(a[0]), "r"(a[1]), "r"(a[2]), "r"(a[3]), "r"(b0), "r"(b1));
}
__device__ __forceinline__ void h8_to_f(const uint4& raw, float* x) {
    __half2 p0 = *reinterpret_cast<const __half2*>(&raw.x);
    __half2 p1 = *reinterpret_cast<const __half2*>(&raw.y);
    __half2 p2 = *reinterpret_cast<const __half2*>(&raw.z);
    __half2 p3 = *reinterpret_cast<const __half2*>(&raw.w);
    x[0] = __half2float(p0.x); x[1] = __half2float(p0.y);
    x[2] = __half2float(p1.x); x[3] = __half2float(p1.y);
    x[4] = __half2float(p2.x); x[5] = __half2float(p2.y);
    x[6] = __half2float(p3.x); x[7] = __half2float(p3.y);
}

// ---------------- CSR build (parallel kernels) ----------------
__global__ void k_zero() {
    int i = blockIdx.x * 256 + threadIdx.x;
    if (i < Nn) g_deg[i] = 0;
    if (i < Nn * NTc) g_hist[i] = 0;
}
__global__ void k_count(const int* __restrict__ ei, const int* __restrict__ ea) {
    int e = blockIdx.x * 256 + threadIdx.x;
    if (e < Ee) {
        int dst = ei[Ee + e];
        atomicAdd(&g_deg[dst], 1);
        atomicAdd(&g_hist[dst * NTc + ea[e]], 1);
    }
}
__global__ void k_scan() {
    __shared__ int part[256];
    int tid = threadIdx.x;
    int base = tid * 32;
    int s = 0;
    for (int i = 0; i < 32; ++i) s += g_deg[base + i];
    part[tid] = s;
    __syncthreads();
    for (int off = 1; off < 256; off <<= 1) {
        int v = (tid >= off) ? part[tid - off] : 0;
        __syncthreads();
        part[tid] += v;
        __syncthreads();
    }
    int run = (tid == 0) ? 0 : part[tid - 1];
    for (int i = 0; i < 32; ++i) {
        int n = base + i;
        g_rowptr[n] = run;
        g_woff[n] = run;
        run += g_deg[n];
    }
    if (tid == 255) g_rowptr[Nn] = run;
}
__global__ void k_fill(const int* __restrict__ ei) {
    int e = blockIdx.x * 256 + threadIdx.x;
    if (e < Ee) {
        int dst = ei[Ee + e];
        int pos = atomicAdd(&g_woff[dst], 1);
        g_spt[pos] = e;
    }
}
__global__ void k_sort(const int* __restrict__ ei, const int* __restrict__ ea) {
    int n = blockIdx.x * 256 + threadIdx.x;
    if (n < Nn) {
        int r0 = g_rowptr[n], r1 = g_rowptr[n + 1];
        for (int i = r0 + 1; i < r1; ++i) {
            int v = g_spt[i];
            int j = i - 1;
            while (j >= r0 && g_spt[j] > v) { g_spt[j + 1] = g_spt[j]; --j; }
            g_spt[j + 1] = v;
        }
        for (int i = r0; i < r1; ++i) {
            int e = g_spt[i];
            g_spt[i] = (ei[e] << 3) | ea[e];
        }
    }
}

// ---------------- fused packing: x, all weights, all tables ----------------
__global__ void __launch_bounds__(256)
k_pack_all(const float* __restrict__ x,
           const float* __restrict__ W_in,
           const float* __restrict__ Wl, const float* __restrict__ Wr,
           const float* __restrict__ W_out,
           const float* __restrict__ edge_emb, const float* __restrict__ We,
           __half* __restrict__ Apk, __half* __restrict__ Bpk) {
    const int bid = blockIdx.x;
    const int tid = threadIdx.x;

    if (bid < Nn) {
        const float4 v = *reinterpret_cast<const float4*>(x + (size_t)bid * DINc + tid * 4);
        __half2 hp0 = {__float2half_rn(v.x), __float2half_rn(v.y)};
        __half2 hp1 = {__float2half_rn(v.z), __float2half_rn(v.w)};
        __half* p = Apk + (size_t)bid * DINc + tid * 4;
        reinterpret_cast<__half2*>(p)[0] = hp0;
        reinterpret_cast<__half2*>(p)[1] = hp1;
        return;
    }
    if (bid < Nn + 256 + 3072 + 64) {
        const float* W; __half* P; int K, N, nb, kb;
        bool dup;
        int id = bid - Nn;
        if (id < 256) {
            W = W_in; P = Bpk + OFF_WIN; K = DINc; N = DHc; dup = false;
            nb = id & 7; kb = id >> 3;
        } else if (id < 256 + 3072) {
            int id2 = id - 256;
            int mat = id2 >> 9;
            int t = id2 & 511;
            int l = mat >> 1, side = mat & 1;
            W = (side == 0 ? Wl : Wr) + (size_t)l * DHc * HDc;
            P = Bpk + OFF_WLR(l) + (size_t)side * HDc * DHc;
            K = DHc; N = HDc; dup = false;
            nb = t & 63; kb = t >> 6;
        } else {
            int id2 = id - 256 - 3072;
            W = W_out; P = Bpk + OFF_WOUT; K = DHc; N = DHc; dup = true;
            nb = id2 & 7; kb = id2 >> 3;
        }
        __shared__ float tbuf[32][33];
        int tx = tid & 31, ty = tid >> 5;
        #pragma unroll
        for (int i = 0; i < 32; i += 8)
            tbuf[ty + i][tx] = W[(size_t)(kb * 32 + ty + i) * N + nb * 32 + tx];
        __syncthreads();
        const int stride = dup ? 2 * K : K;
        #pragma unroll
        for (int i = 0; i < 32; i += 8) {
            int n = nb * 32 + ty + i;
            int k = kb * 32 + tx;
            __half hi = __float2half_rn(tbuf[tx][ty + i]);
            P[(size_t)n * stride + k] = hi;
            if (dup) P[(size_t)n * stride + K + k] = hi;
        }
        return;
    }
    {
        int id = bid - (Nn + 256 + 3072 + 64);
        int lt = id >> 3;
        int jb = id & 7;
        int l = lt / NTc, t = lt % NTc;
        int j = jb * 256 + tid;
        const float* w = We + (size_t)l * DHc * HDc + j;
        const float* e = edge_emb + t * DHc;
        float s = 0.f;
        #pragma unroll 4
        for (int k = 0; k < DHc; ++k) s = fmaf(e[k], w[(size_t)k * HDc], s);
        g_table[(size_t)l * NTc * HDc + t * HDc + j] = s;
    }
}

// ---------------- GEMM kernel 1 (proj): CTA 128x128, warp 32x64, 3-stage, 2 CTA/SM ----
#define GSTAGE 3
#define STG_BYTES 32768
#define GEMM_SMEM (GSTAGE * STG_BYTES)

__global__ void __launch_bounds__(256, 2)
k_gemm_mma(const __half* __restrict__ A, int lda, const __half* __restrict__ B,
           const float* __restrict__ bias, float* __restrict__ C, int Ktot, int Nc,
           const float* __restrict__ emb, const int* __restrict__ types,
           __half* __restrict__ packA) {
    extern __shared__ __align__(1024) char smem[];
    const uint32_t sb = smem_u32(smem);
    const int tid = threadIdx.x;
    const int lane = tid & 31, w = tid >> 5;
    const int wm = w & 3, wn = w >> 2;
    const int row0 = blockIdx.y * 128;
    const int col0 = blockIdx.x * 128;
    const int nch = Ktot >> 6;

    float acc[2][8][4];
    #pragma unroll
    for (int i = 0; i < 2; ++i)
        #pragma unroll
        for (int j = 0; j < 8; ++j)
            #pragma unroll
            for (int q = 0; q < 4; ++q) acc[i][j][q] = 0.f;

    uint32_t sm_off[4];
    const __half* gA[4];
    const __half* gB[4];
    #pragma unroll
    for (int u = 0; u < 4; ++u) {
        int i = tid + u * 256;
        int r = i >> 3, seg = i & 7;
        uint32_t off = (uint32_t)(r * 128 + seg * 16);
        sm_off[u] = off ^ ((off >> 3) & 0x70);
        gA[u] = A + (size_t)(row0 + r) * lda + (seg << 3);
        gB[u] = B + (size_t)(col0 + r) * Ktot + (seg << 3);
    }
    auto load_chunk = [&](int c) {
        const uint32_t s = sb + (uint32_t)((c % GSTAGE) * STG_BYTES);
        const int kof = c << 6;
        #pragma unroll
        for (int u = 0; u < 4; ++u) cp16(s + sm_off[u], gA[u] + kof);
        #pragma unroll
        for (int u = 0; u < 4; ++u) cp16(s + 16384 + sm_off[u], gB[u] + kof);
        asm volatile("cp.async.commit_group;");
    };
    #pragma unroll
    for (int c = 0; c < GSTAGE - 1; ++c) load_chunk(c);

    uint32_t a_base[2], a_swz[2];
    #pragma unroll
    for (int mb = 0; mb < 2; ++mb) {
        int row = wm * 32 + mb * 16 + (lane & 15);
        a_base[mb] = (uint32_t)(row * 128 + ((lane >> 4) << 4));
        a_swz[mb] = (uint32_t)((row & 7) << 4);
    }
    uint32_t b_base[4], b_swz[4];
    #pragma unroll
    for (int nb = 0; nb < 4; ++nb) {
        int row = wn * 64 + nb * 16 + (lane & 7) + ((lane >> 4) << 3);
        b_base[nb] = (uint32_t)(row * 128 + (((lane >> 3) & 1) << 4));
        b_swz[nb] = (uint32_t)((row & 7) << 4);
    }

    for (int c = 0; c < nch; ++c) {
        asm volatile("cp.async.wait_group %0;" :: "n"(GSTAGE - 2));
        __syncthreads();
        if (c + GSTAGE - 1 < nch) load_chunk(c + GSTAGE - 1);
        else asm volatile("cp.async.commit_group;");
        const uint32_t stb = sb + (uint32_t)((c % GSTAGE) * STG_BYTES);
        #pragma unroll
        for (int kk = 0; kk < 4; ++kk) {
            const uint32_t kby = (uint32_t)(kk * 32);
            uint32_t a[2][4];
            #pragma unroll
            for (int mb = 0; mb < 2; ++mb)
                ldsm_x4(a[mb], stb + ((a_base[mb] + kby) ^ a_swz[mb]));
            uint32_t b[4][4];
            #pragma unroll
            for (int nb = 0; nb < 4; ++nb)
                ldsm_x4(b[nb], stb + 16384 + ((b_base[nb] + kby) ^ b_swz[nb]));
            #pragma unroll
            for (int mb = 0; mb < 2; ++mb)
                #pragma unroll
                for (int nb = 0; nb < 4; ++nb) {
                    mma_f16(acc[mb][2 * nb],     a[mb], b[nb][0], b[nb][1]);
                    mma_f16(acc[mb][2 * nb + 1], a[mb], b[nb][2], b[nb][3]);
                }
        }
    }

    const int r_base = row0 + wm * 32 + (lane >> 2);
    const int c_base = col0 + wn * 64 + ((lane & 3) << 1);
    const int K2 = 2 * Nc;
    #pragma unroll
    for (int mb = 0; mb < 2; ++mb) {
        const int r1 = r_base + mb * 16;
        const int r2 = r1 + 8;
        #pragma unroll
        for (int nt = 0; nt < 8; ++nt) {
            const int col = c_base + nt * 8;
            float bx = bias[col], by = bias[col + 1];
            float e1x = 0.f, e1y = 0.f, e2x = 0.f, e2y = 0.f;
            if (emb) {
                const float* em1 = emb + (size_t)types[r1] * Nc + col;
                const float* em2 = emb + (size_t)types[r2] * Nc + col;
                e1x = em1[0]; e1y = em1[1]; e2x = em2[0]; e2y = em2[1];
            }
            float v00 = acc[mb][nt][0] + bx + e1x;
            float v01 = acc[mb][nt][1] + by + e1y;
            float v10 = acc[mb][nt][2] + bx + e2x;
            float v11 = acc[mb][nt][3] + by + e2y;
            if (C) {
                float2 t0 = {v00, v01}, t1 = {v10, v11};
                *reinterpret_cast<float2*>(&C[(size_t)r1 * Nc + col]) = t0;
                *reinterpret_cast<float2*>(&C[(size_t)r2 * Nc + col]) = t1;
            }
            if (packA) {
                __half h00 = __float2half_rn(v00);
                __half h01 = __float2half_rn(v01);
                __half h10 = __float2half_rn(v10);
                __half h11 = __float2half_rn(v11);
                __half2 hp1 = {h00, h01};
                __half2 hp2 = {h10, h11};
                __half2 lp1 = {__float2half_rn(v00 - __half2float(h00)),
                               __float2half_rn(v01 - __half2float(h01))};
                __half2 lp2 = {__float2half_rn(v10 - __half2float(h10)),
                               __float2half_rn(v11 - __half2float(h11))};
                __half* p1 = packA + (size_t)r1 * K2 + col;
                __half* p2 = packA + (size_t)r2 * K2 + col;
                *reinterpret_cast<__half2*>(p1)      = hp1;
                *reinterpret_cast<__half2*>(p1 + Nc) = lp1;
                *reinterpret_cast<__half2*>(p2)      = hp2;
                *reinterpret_cast<__half2*>(p2 + Nc) = lp2;
            }
        }
    }
}

// ---------------- GEMM kernel 2: PERSISTENT merged xl|xr GEMM ----------------
// grid = 148 CTAs; each sweeps tiles (128x256) with a continuous cp.async ring.
#define BGSTAGE 4
#define BSTG_BYTES 49152
#define BGEMM_SMEM (BGSTAGE * BSTG_BYTES)
#define BGRID 148

__global__ void __launch_bounds__(256, 1)
k_gemm_big(const __half* __restrict__ A, int lda, const __half* __restrict__ B,
           const float* __restrict__ bias, const float* __restrict__ bias2, int halfN,
           __half* __restrict__ C, int Ktot, int Nc) {
    extern __shared__ __align__(1024) char smem[];
    const uint32_t sb = smem_u32(smem);
    const int tid = threadIdx.x;
    const int lane = tid & 31, w = tid >> 5;
    const int wm = w & 1, wn = w >> 1;
    const int nch = Ktot >> 6;                 // 4
    const int tilesX = Nc >> 8;                // 16
    const int total = tilesX * (Nn >> 7);      // 1024
    const int grid = gridDim.x;
    const int bid = blockIdx.x;
    const int my_tiles = (total - bid + grid - 1) / grid;
    const int total_q = my_tiles * nch;

    // per-thread load geometry (pointers without tile offset)
    uint32_t sm_offA[4], sm_offB[8];
    const __half* baseA[4];
    const __half* baseB[8];
    #pragma unroll
    for (int u = 0; u < 4; ++u) {
        int i = tid + u * 256;
        int r = i >> 3, seg = i & 7;
        uint32_t off = (uint32_t)(r * 128 + seg * 16);
        sm_offA[u] = off ^ ((off >> 3) & 0x70);
        baseA[u] = A + (size_t)r * lda + (seg << 3);
    }
    #pragma unroll
    for (int u = 0; u < 8; ++u) {
        int i = tid + u * 256;
        int r = i >> 3, seg = i & 7;
        uint32_t off = (uint32_t)(r * 128 + seg * 16);
        sm_offB[u] = off ^ ((off >> 3) & 0x70);
        baseB[u] = B + (size_t)r * Ktot + (seg << 3);
    }

    auto issue = [&](int q) {
        const int mt = q / nch;
        const int c = q - mt * nch;
        const int tt = bid + mt * grid;
        const int ty = tt / tilesX;
        const int tx = tt - ty * tilesX;
        const size_t aofs = (size_t)(ty << 7) * lda + (c << 6);
        const size_t bofs = (size_t)(tx << 8) * Ktot + (c << 6);
        const uint32_t s = sb + (uint32_t)((q % BGSTAGE) * BSTG_BYTES);
        #pragma unroll
        for (int u = 0; u < 4; ++u) cp16(s + sm_offA[u], baseA[u] + aofs);
        #pragma unroll
        for (int u = 0; u < 8; ++u) cp16(s + 16384 + sm_offB[u], baseB[u] + bofs);
        asm volatile("cp.async.commit_group;");
    };

    uint32_t a_base[4], a_swz[4];
    #pragma unroll
    for (int mb = 0; mb < 4; ++mb) {
        int row = wm * 64 + mb * 16 + (lane & 15);
        a_base[mb] = (uint32_t)(row * 128 + ((lane >> 4) << 4));
        a_swz[mb] = (uint32_t)((row & 7) << 4);
    }
    uint32_t b_base[4], b_swz[4];
    #pragma unroll
    for (int nb = 0; nb < 4; ++nb) {
        int row = wn * 64 + nb * 16 + (lane & 7) + ((lane >> 4) << 3);
        b_base[nb] = (uint32_t)(row * 128 + (((lane >> 3) & 1) << 4));
        b_swz[nb] = (uint32_t)((row & 7) << 4);
    }

    // prologue: fill pipeline across tile boundaries
    int q_load = 0;
    #pragma unroll
    for (int i = 0; i < BGSTAGE - 1; ++i)
        if (q_load < total_q) { issue(q_load); ++q_load; }

    int q_comp = 0;
    for (int mt = 0; mt < my_tiles; ++mt) {
        const int tt = bid + mt * grid;
        const int ty = tt / tilesX;
        const int tx = tt - ty * tilesX;
        const int row0 = ty << 7;
        const int col0 = tx << 8;

        float acc[4][8][4];
        #pragma unroll
        for (int i = 0; i < 4; ++i)
            #pragma unroll
            for (int j = 0; j < 8; ++j)
                #pragma unroll
                for (int q = 0; q < 4; ++q) acc[i][j][q] = 0.f;

        for (int c = 0; c < nch; ++c) {
            asm volatile("cp.async.wait_group %0;" :: "n"(BGSTAGE - 2));
            __syncthreads();
            if (q_load < total_q) { issue(q_load); ++q_load; }
            else asm volatile("cp.async.commit_group;");
            const uint32_t stb = sb + (uint32_t)((q_comp % BGSTAGE) * BSTG_BYTES);
            ++q_comp;
            #pragma unroll
            for (int kk = 0; kk < 4; ++kk) {
                const uint32_t kby = (uint32_t)(kk * 32);
                uint32_t a[4][4];
                #pragma unroll
                for (int mb = 0; mb < 4; ++mb)
                    ldsm_x4(a[mb], stb + ((a_base[mb] + kby) ^ a_swz[mb]));
                uint32_t b[4][4];
                #pragma unroll
                for (int nb = 0; nb < 4; ++nb)
                    ldsm_x4(b[nb], stb + 16384 + ((b_base[nb] + kby) ^ b_swz[nb]));
                #pragma unroll
                for (int mb = 0; mb < 4; ++mb)
                    #pragma unroll
                    for (int nb = 0; nb < 4; ++nb) {
                        mma_f16(acc[mb][2 * nb],     a[mb], b[nb][0], b[nb][1]);
                        mma_f16(acc[mb][2 * nb + 1], a[mb], b[nb][2], b[nb][3]);
                    }
            }
        }

        // epilogue (register-only; in-flight loads for next tile are unaffected)
        const float* bp = bias;
        int cadj = 0;
        if (bias2 && col0 >= halfN) { bp = bias2; cadj = halfN; }
        const int r_base = row0 + wm * 64 + (lane >> 2);
        const int c_base = col0 + wn * 64 + ((lane & 3) << 1);
        #pragma unroll
        for (int mb = 0; mb < 4; ++mb) {
            const int r1 = r_base + mb * 16;
            const int r2 = r1 + 8;
            #pragma unroll
            for (int nt = 0; nt < 8; ++nt) {
                const int col = c_base + nt * 8;
                float bx = bp[col - cadj], by = bp[col + 1 - cadj];
                __half2 t0 = __floats2half2_rn(acc[mb][nt][0] + bx, acc[mb][nt][1] + by);
                __half2 t1 = __floats2half2_rn(acc[mb][nt][2] + bx, acc[mb][nt][3] + by);
                *reinterpret_cast<__half2*>(&C[(size_t)r1 * Nc + col]) = t0;
                *reinterpret_cast<__half2*>(&C[(size_t)r2 * Nc + col]) = t1;
            }
        }
    }
}

// ---------------- fused GATv2 edge kernel: registered att/xr/lee, spt metadata -------
#define EDGE_SMEM (6 * HDc * 4)

__global__ void __launch_bounds__(256)
k_edge(const float* __restrict__ att_l, const float* __restrict__ bgat_l,
       int loff, __half* __restrict__ packH) {
    extern __shared__ float sm[];
    float* s_tab = sm;
    float* s_out = sm + 5 * HDc;

    const int tid = threadIdx.x;
    const int lane = tid & 31;
    const int base = ((tid >> 5) << 8) + (lane << 3);

    const float* tb = g_table + loff;
    #pragma unroll
    for (int u = 0; u < 40; ++u) s_tab[tid + u * 256] = tb[tid + u * 256];
    float att[8];
    {
        float4 a0 = *reinterpret_cast<const float4*>(att_l + base);
        float4 a1 = *reinterpret_cast<const float4*>(att_l + base + 4);
        att[0]=a0.x; att[1]=a0.y; att[2]=a0.z; att[3]=a0.w;
        att[4]=a1.x; att[5]=a1.y; att[6]=a1.z; att[7]=a1.w;
    }
    const float bg0 = bgat_l[tid];
    __syncthreads();

    for (int g = 0; g < EGc; ++g) {
        const int n = blockIdx.x * EGc + g;
        const int r0 = g_rowptr[n], r1 = g_rowptr[n + 1];
        const int deg = r1 - r0;
        const float inv = 1.0f / (float)(deg > 1 ? deg : 1);

        float c0 = (float)g_hist[n * NTc + 0];
        float c1 = (float)g_hist[n * NTc + 1];
        float c2 = (float)g_hist[n * NTc + 2];
        float c3 = (float)g_hist[n * NTc + 3];
        float c4 = (float)g_hist[n * NTc + 4];

        float xr[8];
        {
            uint4 raw = *reinterpret_cast<const uint4*>(g_xlr + (size_t)n * N2c + HDc + base);
            h8_to_f(raw, xr);
        }
        float lee[8];
        #pragma unroll
        for (int i = 0; i < 8; ++i) {
            float v = c0 * s_tab[0 * HDc + base + i];
            v = fmaf(c1, s_tab[1 * HDc + base + i], v);
            v = fmaf(c2, s_tab[2 * HDc + base + i], v);
            v = fmaf(c3, s_tab[3 * HDc + base + i], v);
            v = fmaf(c4, s_tab[4 * HDc + base + i], v);
            lee[i] = v * inv;
        }

        float m = -1e30f, d = 0.f;
        float acc[8];
        #pragma unroll
        for (int i = 0; i < 8; ++i) acc[i] = 0.f;

        auto fetch = [&](int idx, int& s, int& t) {
            if (idx < r1) { int pk = g_spt[idx]; s = pk >> 3; t = pk & 7; }
            else { s = n; t = -1; }
        };
        int s_c, t_c, s_n, t_n;
        fetch(r0, s_c, t_c);
        uint4 raw_c = *reinterpret_cast<const uint4*>(g_xlr + (size_t)s_c * N2c + base);
        fetch(r0 + 1, s_n, t_n);

        for (int idx = r0; idx <= r1; ++idx) {
            uint4 raw_n = *reinterpret_cast<const uint4*>(g_xlr + (size_t)s_n * N2c + base);
            int s_nn, t_nn;
            fetch(idx + 2, s_nn, t_nn);

            float xlv[8];
            h8_to_f(raw_c, xlv);
            float part = 0.f;
            if (t_c < 0) {
                #pragma unroll
                for (int i = 0; i < 8; ++i) {
                    float z = xlv[i] + xr[i] + lee[i];
                    z = z > 0.f ? z : 0.2f * z;
                    part = fmaf(z, att[i], part);
                }
            } else {
                const float* tab = s_tab + t_c * HDc + base;
                #pragma unroll
                for (int i = 0; i < 8; ++i) {
                    float z = xlv[i] + xr[i] + tab[i];
                    z = z > 0.f ? z : 0.2f * z;
                    part = fmaf(z, att[i], part);
                }
            }
            #pragma unroll
            for (int o = 16; o > 0; o >>= 1)
                part += __shfl_xor_sync(0xffffffffu, part, o);

            float mn = fmaxf(m, part);
            float sc = __expf(m - mn);
            float p  = __expf(part - mn);
            d = d * sc + p;
            #pragma unroll
            for (int i = 0; i < 8; ++i) acc[i] = fmaf(acc[i], sc, p * xlv[i]);
            m = mn;

            raw_c = raw_n; t_c = t_n;
            s_n = s_nn; t_n = t_nn;
        }

        float invd = 1.0f / d;
        #pragma unroll
        for (int i = 0; i < 8; ++i) s_out[base + i] = acc[i] * invd;
        __syncthreads();

        {
            int c = tid;
            float v = 0.f;
            #pragma unroll
            for (int h = 0; h < HHc; ++h) v += s_out[h * DHc + c];
            v = fmaf(v, 0.125f, bg0);
            v = fmaxf(v, 0.f);
            __half hi = __float2half_rn(v);
            __half lo = __float2half_rn(v - __half2float(hi));
            __half* p = packH + (size_t)n * (2 * DHc) + c;
            p[0]   = hi;
            p[DHc] = lo;
        }
        __syncthreads();
    }
}

// ---------------- host orchestration ----------------
extern "C" void kernel_launch(void* const* d_in, const int* in_sizes, int n_in,
                              void* d_out, int out_size) {
    const float* x         = (const float*)d_in[0];
    const int*   edge_index= (const int*)  d_in[1];
    const int*   edge_attr = (const int*)  d_in[2];
    const int*   node_types= (const int*)  d_in[3];
    const float* W_in      = (const float*)d_in[4];
    const float* b_in      = (const float*)d_in[5];
    const float* node_emb  = (const float*)d_in[6];
    const float* edge_emb  = (const float*)d_in[7];
    const float* Wl        = (const float*)d_in[8];
    const float* bl        = (const float*)d_in[9];
    const float* Wr        = (const float*)d_in[10];
    const float* br        = (const float*)d_in[11];
    const float* We        = (const float*)d_in[12];
    const float* att       = (const float*)d_in[13];
    const float* b_gat     = (const float*)d_in[14];
    const float* W_out     = (const float*)d_in[15];
    const float* b_out     = (const float*)d_in[16];
    float* out = (float*)d_out;

    __half* xlr;    cudaGetSymbolAddress((void**)&xlr, g_xlr);
    __half* Apk;    cudaGetSymbolAddress((void**)&Apk, g_Apack);
    __half* Hpk;    cudaGetSymbolAddress((void**)&Hpk, g_hpack);
    __half* Bpk;    cudaGetSymbolAddress((void**)&Bpk, g_Bpack);

    cudaFuncSetAttribute(k_gemm_mma, cudaFuncAttributeMaxDynamicSharedMemorySize, GEMM_SMEM);
    cudaFuncSetAttribute(k_gemm_big, cudaFuncAttributeMaxDynamicSharedMemorySize, BGEMM_SMEM);
    cudaFuncSetAttribute(k_edge, cudaFuncAttributeMaxDynamicSharedMemorySize, EDGE_SMEM);

    // 1: pack everything
    k_pack_all<<<Nn + 256 + 3072 + 64 + 120, 256>>>(x, W_in, Wl, Wr, W_out,
                                                    edge_emb, We, Apk, Bpk);
    // 2: CSR zero
    k_zero<<<(Nn * NTc + 255) / 256, 256>>>();
    // 3: input projection -> packed h0
    k_gemm_mma<<<dim3(2, 64), 256, GEMM_SMEM>>>(
        Apk, DINc, Bpk + OFF_WIN, b_in, nullptr, DINc, DHc, node_emb, node_types, Hpk);
    // 4: persistent merged xl|xr GEMM layer 0   <- ncu capture slot
    k_gemm_big<<<BGRID, 256, BGEMM_SMEM>>>(
        Hpk, 2 * DHc, Bpk + OFF_WLR(0), bl, br, HDc, xlr, DHc, N2c);
    // 5-8: finish CSR
    k_count<<<(Ee + 255) / 256, 256>>>(edge_index, edge_attr);
    k_scan<<<1, 256>>>();
    k_fill<<<(Ee + 255) / 256, 256>>>(edge_index);
    k_sort<<<(Nn + 255) / 256, 256>>>(edge_index, edge_attr);

    for (int l = 0; l < LLc; ++l) {
        if (l > 0) {
            k_gemm_big<<<BGRID, 256, BGEMM_SMEM>>>(
                Hpk, 2 * DHc, Bpk + OFF_WLR(l), bl + (size_t)l * HDc, br + (size_t)l * HDc,
                HDc, xlr, DHc, N2c);
        }
        k_edge<<<Nn / EGc, 256, EDGE_SMEM>>>(att + (size_t)l * HHc * DHc,
                                             b_gat + (size_t)l * DHc,
                                             l * NTc * HDc, Hpk);
    }

    // output projection -> d_out fp32
    k_gemm_mma<<<dim3(2, 64), 256, GEMM_SMEM>>>(
        Hpk, 2 * DHc, Bpk + OFF_WOUT, b_out, out, 2 * DHc, DHc, nullptr, nullptr, nullptr);

    (void)in_sizes; (void)n_in; (void)out_size;
}

// round 16
// speedup vs baseline: 1.0758x; 1.0758x over previous
#include <cuda_runtime.h>
#include <cuda_fp16.h>
#include <math.h>
#include <stdint.h>

// Problem constants
#define Nn   8192
#define Ee   32768
#define DINc 1024
#define DHc  256
#define HHc  8
#define LLc  3
#define HDc  2048   // H*DH
#define NTc  5
#define N2c  4096   // merged Wl|Wr output width
#define EGc  8      // nodes per edge-kernel block

// ---------------- device scratch ----------------
__device__ __half g_xlr[(size_t)Nn * N2c];
__device__ float g_table[LLc * NTc * HDc];
__device__ int   g_deg[Nn];
__device__ int   g_hist[Nn * NTc];
__device__ int   g_rowptr[Nn + 1];
__device__ int   g_woff[Nn];
__device__ int   g_spt[Ee];

__device__ __half g_Apack[(size_t)Nn * DINc];
__device__ __half g_hpack[(size_t)Nn * 2 * DHc];
__device__ __half g_Bpack[4000000];

#define OFF_WIN  0
#define SZ_WIN   (DHc * DINc)
#define SZ_L     ((size_t)N2c * DHc)
#define OFF_WLR(l) (SZ_WIN + (size_t)(l) * SZ_L)
#define OFF_WOUT (SZ_WIN + (size_t)3 * SZ_L)

// ---------------- PTX helpers ----------------
__device__ __forceinline__ uint32_t smem_u32(const void* p) {
    uint32_t a;
    asm("{ .reg .u64 t; cvta.to.shared.u64 t, %1; cvt.u32.u64 %0, t; }" : "=r"(a) : "l"(p));
    return a;
}
__device__ __forceinline__ void cp16(uint32_t d, const void* g) {
    asm volatile("cp.async.cg.shared.global [%0], [%1], 16;" :: "r"(d), "l"(g));
}
__device__ __forceinline__ void ldsm_x4(uint32_t* r, uint32_t addr) {
    asm volatile("ldmatrix.sync.aligned.m8n8.x4.shared.b16 {%0,%1,%2,%3}, [%4];"
                 : "=r"(r[0]), "=r"(r[1]), "=r"(r[2]), "=r"(r[3]) : "r"(addr));
}
__device__ __forceinline__ void mma_f16(float* c, const uint32_t* a, uint32_t b0, uint32_t b1) {
    asm volatile(
        "mma.sync.aligned.m16n8k16.row.col.f32.f16.f16.f32 "
        "{%0,%1,%2,%3}, {%4,%5,%6,%7}, {%8,%9}, {%0,%1,%2,%3};"
        : "+f"(c[0]), "+f"(c[1]), "+f"(c[2]), "+f"(c[3])
        : "r"(a[0]), "r"(a[1]), "r"(a[2]), "r"(a[3]), "r"(b0), "r"(b1));
}
__device__ __forceinline__ void h8_to_f(const uint4& raw, float* x) {
    __half2 p0 = *reinterpret_cast<const __half2*>(&raw.x);
    __half2 p1 = *reinterpret_cast<const __half2*>(&raw.y);
    __half2 p2 = *reinterpret_cast<const __half2*>(&raw.z);
    __half2 p3 = *reinterpret_cast<const __half2*>(&raw.w);
    x[0] = __half2float(p0.x); x[1] = __half2float(p0.y);
    x[2] = __half2float(p1.x); x[3] = __half2float(p1.y);
    x[4] = __half2float(p2.x); x[5] = __half2float(p2.y);
    x[6] = __half2float(p3.x); x[7] = __half2float(p3.y);
}

// ---------------- CSR build (parallel kernels, forked stream) ----------------
__global__ void k_zero() {
    int i = blockIdx.x * 256 + threadIdx.x;
    if (i < Nn) g_deg[i] = 0;
    if (i < Nn * NTc) g_hist[i] = 0;
}
__global__ void k_count(const int* __restrict__ ei, const int* __restrict__ ea) {
    int e = blockIdx.x * 256 + threadIdx.x;
    if (e < Ee) {
        int dst = ei[Ee + e];
        atomicAdd(&g_deg[dst], 1);
        atomicAdd(&g_hist[dst * NTc + ea[e]], 1);
    }
}
__global__ void k_scan() {
    __shared__ int part[256];
    int tid = threadIdx.x;
    int base = tid * 32;
    int s = 0;
    for (int i = 0; i < 32; ++i) s += g_deg[base + i];
    part[tid] = s;
    __syncthreads();
    for (int off = 1; off < 256; off <<= 1) {
        int v = (tid >= off) ? part[tid - off] : 0;
        __syncthreads();
        part[tid] += v;
        __syncthreads();
    }
    int run = (tid == 0) ? 0 : part[tid - 1];
    for (int i = 0; i < 32; ++i) {
        int n = base + i;
        g_rowptr[n] = run;
        g_woff[n] = run;
        run += g_deg[n];
    }
    if (tid == 255) g_rowptr[Nn] = run;
}
__global__ void k_fill(const int* __restrict__ ei) {
    int e = blockIdx.x * 256 + threadIdx.x;
    if (e < Ee) {
        int dst = ei[Ee + e];
        int pos = atomicAdd(&g_woff[dst], 1);
        g_spt[pos] = e;
    }
}
__global__ void k_sort(const int* __restrict__ ei, const int* __restrict__ ea) {
    int n = blockIdx.x * 256 + threadIdx.x;
    if (n < Nn) {
        int r0 = g_rowptr[n], r1 = g_rowptr[n + 1];
        for (int i = r0 + 1; i < r1; ++i) {
            int v = g_spt[i];
            int j = i - 1;
            while (j >= r0 && g_spt[j] > v) { g_spt[j + 1] = g_spt[j]; --j; }
            g_spt[j + 1] = v;
        }
        for (int i = r0; i < r1; ++i) {
            int e = g_spt[i];
            g_spt[i] = (ei[e] << 3) | ea[e];
        }
    }
}

// ---------------- fused packing: x, all weights, all tables ----------------
__global__ void __launch_bounds__(256)
k_pack_all(const float* __restrict__ x,
           const float* __restrict__ W_in,
           const float* __restrict__ Wl, const float* __restrict__ Wr,
           const float* __restrict__ W_out,
           const float* __restrict__ edge_emb, const float* __restrict__ We,
           __half* __restrict__ Apk, __half* __restrict__ Bpk) {
    const int bid = blockIdx.x;
    const int tid = threadIdx.x;

    if (bid < Nn) {
        const float4 v = *reinterpret_cast<const float4*>(x + (size_t)bid * DINc + tid * 4);
        __half2 hp0 = {__float2half_rn(v.x), __float2half_rn(v.y)};
        __half2 hp1 = {__float2half_rn(v.z), __float2half_rn(v.w)};
        __half* p = Apk + (size_t)bid * DINc + tid * 4;
        reinterpret_cast<__half2*>(p)[0] = hp0;
        reinterpret_cast<__half2*>(p)[1] = hp1;
        return;
    }
    if (bid < Nn + 256 + 3072 + 64) {
        const float* W; __half* P; int K, N, nb, kb;
        bool dup;
        int id = bid - Nn;
        if (id < 256) {
            W = W_in; P = Bpk + OFF_WIN; K = DINc; N = DHc; dup = false;
            nb = id & 7; kb = id >> 3;
        } else if (id < 256 + 3072) {
            int id2 = id - 256;
            int mat = id2 >> 9;
            int t = id2 & 511;
            int l = mat >> 1, side = mat & 1;
            W = (side == 0 ? Wl : Wr) + (size_t)l * DHc * HDc;
            P = Bpk + OFF_WLR(l) + (size_t)side * HDc * DHc;
            K = DHc; N = HDc; dup = false;
            nb = t & 63; kb = t >> 6;
        } else {
            int id2 = id - 256 - 3072;
            W = W_out; P = Bpk + OFF_WOUT; K = DHc; N = DHc; dup = true;
            nb = id2 & 7; kb = id2 >> 3;
        }
        __shared__ float tbuf[32][33];
        int tx = tid & 31, ty = tid >> 5;
        #pragma unroll
        for (int i = 0; i < 32; i += 8)
            tbuf[ty + i][tx] = W[(size_t)(kb * 32 + ty + i) * N + nb * 32 + tx];
        __syncthreads();
        const int stride = dup ? 2 * K : K;
        #pragma unroll
        for (int i = 0; i < 32; i += 8) {
            int n = nb * 32 + ty + i;
            int k = kb * 32 + tx;
            __half hi = __float2half_rn(tbuf[tx][ty + i]);
            P[(size_t)n * stride + k] = hi;
            if (dup) P[(size_t)n * stride + K + k] = hi;
        }
        return;
    }
    {
        int id = bid - (Nn + 256 + 3072 + 64);
        int lt = id >> 3;
        int jb = id & 7;
        int l = lt / NTc, t = lt % NTc;
        int j = jb * 256 + tid;
        const float* w = We + (size_t)l * DHc * HDc + j;
        const float* e = edge_emb + t * DHc;
        float s = 0.f;
        #pragma unroll 4
        for (int k = 0; k < DHc; ++k) s = fmaf(e[k], w[(size_t)k * HDc], s);
        g_table[(size_t)l * NTc * HDc + t * HDc + j] = s;
    }
}

// ---------------- GEMM kernel 1 (proj): CTA 128x128, warp 32x64, 3-stage, 2 CTA/SM ----
#define GSTAGE 3
#define STG_BYTES 32768
#define GEMM_SMEM (GSTAGE * STG_BYTES)

__global__ void __launch_bounds__(256, 2)
k_gemm_mma(const __half* __restrict__ A, int lda, const __half* __restrict__ B,
           const float* __restrict__ bias, float* __restrict__ C, int Ktot, int Nc,
           const float* __restrict__ emb, const int* __restrict__ types,
           __half* __restrict__ packA) {
    extern __shared__ __align__(1024) char smem[];
    const uint32_t sb = smem_u32(smem);
    const int tid = threadIdx.x;
    const int lane = tid & 31, w = tid >> 5;
    const int wm = w & 3, wn = w >> 2;
    const int row0 = blockIdx.y * 128;
    const int col0 = blockIdx.x * 128;
    const int nch = Ktot >> 6;

    float acc[2][8][4];
    #pragma unroll
    for (int i = 0; i < 2; ++i)
        #pragma unroll
        for (int j = 0; j < 8; ++j)
            #pragma unroll
            for (int q = 0; q < 4; ++q) acc[i][j][q] = 0.f;

    uint32_t sm_off[4];
    const __half* gA[4];
    const __half* gB[4];
    #pragma unroll
    for (int u = 0; u < 4; ++u) {
        int i = tid + u * 256;
        int r = i >> 3, seg = i & 7;
        uint32_t off = (uint32_t)(r * 128 + seg * 16);
        sm_off[u] = off ^ ((off >> 3) & 0x70);
        gA[u] = A + (size_t)(row0 + r) * lda + (seg << 3);
        gB[u] = B + (size_t)(col0 + r) * Ktot + (seg << 3);
    }
    auto load_chunk = [&](int c) {
        const uint32_t s = sb + (uint32_t)((c % GSTAGE) * STG_BYTES);
        const int kof = c << 6;
        #pragma unroll
        for (int u = 0; u < 4; ++u) cp16(s + sm_off[u], gA[u] + kof);
        #pragma unroll
        for (int u = 0; u < 4; ++u) cp16(s + 16384 + sm_off[u], gB[u] + kof);
        asm volatile("cp.async.commit_group;");
    };
    #pragma unroll
    for (int c = 0; c < GSTAGE - 1; ++c) load_chunk(c);

    uint32_t a_base[2], a_swz[2];
    #pragma unroll
    for (int mb = 0; mb < 2; ++mb) {
        int row = wm * 32 + mb * 16 + (lane & 15);
        a_base[mb] = (uint32_t)(row * 128 + ((lane >> 4) << 4));
        a_swz[mb] = (uint32_t)((row & 7) << 4);
    }
    uint32_t b_base[4], b_swz[4];
    #pragma unroll
    for (int nb = 0; nb < 4; ++nb) {
        int row = wn * 64 + nb * 16 + (lane & 7) + ((lane >> 4) << 3);
        b_base[nb] = (uint32_t)(row * 128 + (((lane >> 3) & 1) << 4));
        b_swz[nb] = (uint32_t)((row & 7) << 4);
    }

    for (int c = 0; c < nch; ++c) {
        asm volatile("cp.async.wait_group %0;" :: "n"(GSTAGE - 2));
        __syncthreads();
        if (c + GSTAGE - 1 < nch) load_chunk(c + GSTAGE - 1);
        else asm volatile("cp.async.commit_group;");
        const uint32_t stb = sb + (uint32_t)((c % GSTAGE) * STG_BYTES);
        #pragma unroll
        for (int kk = 0; kk < 4; ++kk) {
            const uint32_t kby = (uint32_t)(kk * 32);
            uint32_t a[2][4];
            #pragma unroll
            for (int mb = 0; mb < 2; ++mb)
                ldsm_x4(a[mb], stb + ((a_base[mb] + kby) ^ a_swz[mb]));
            uint32_t b[4][4];
            #pragma unroll
            for (int nb = 0; nb < 4; ++nb)
                ldsm_x4(b[nb], stb + 16384 + ((b_base[nb] + kby) ^ b_swz[nb]));
            #pragma unroll
            for (int mb = 0; mb < 2; ++mb)
                #pragma unroll
                for (int nb = 0; nb < 4; ++nb) {
                    mma_f16(acc[mb][2 * nb],     a[mb], b[nb][0], b[nb][1]);
                    mma_f16(acc[mb][2 * nb + 1], a[mb], b[nb][2], b[nb][3]);
                }
        }
    }

    const int r_base = row0 + wm * 32 + (lane >> 2);
    const int c_base = col0 + wn * 64 + ((lane & 3) << 1);
    const int K2 = 2 * Nc;
    #pragma unroll
    for (int mb = 0; mb < 2; ++mb) {
        const int r1 = r_base + mb * 16;
        const int r2 = r1 + 8;
        #pragma unroll
        for (int nt = 0; nt < 8; ++nt) {
            const int col = c_base + nt * 8;
            float bx = bias[col], by = bias[col + 1];
            float e1x = 0.f, e1y = 0.f, e2x = 0.f, e2y = 0.f;
            if (emb) {
                const float* em1 = emb + (size_t)types[r1] * Nc + col;
                const float* em2 = emb + (size_t)types[r2] * Nc + col;
                e1x = em1[0]; e1y = em1[1]; e2x = em2[0]; e2y = em2[1];
            }
            float v00 = acc[mb][nt][0] + bx + e1x;
            float v01 = acc[mb][nt][1] + by + e1y;
            float v10 = acc[mb][nt][2] + bx + e2x;
            float v11 = acc[mb][nt][3] + by + e2y;
            if (C) {
                float2 t0 = {v00, v01}, t1 = {v10, v11};
                *reinterpret_cast<float2*>(&C[(size_t)r1 * Nc + col]) = t0;
                *reinterpret_cast<float2*>(&C[(size_t)r2 * Nc + col]) = t1;
            }
            if (packA) {
                __half h00 = __float2half_rn(v00);
                __half h01 = __float2half_rn(v01);
                __half h10 = __float2half_rn(v10);
                __half h11 = __float2half_rn(v11);
                __half2 hp1 = {h00, h01};
                __half2 hp2 = {h10, h11};
                __half2 lp1 = {__float2half_rn(v00 - __half2float(h00)),
                               __float2half_rn(v01 - __half2float(h01))};
                __half2 lp2 = {__float2half_rn(v10 - __half2float(h10)),
                               __float2half_rn(v11 - __half2float(h11))};
                __half* p1 = packA + (size_t)r1 * K2 + col;
                __half* p2 = packA + (size_t)r2 * K2 + col;
                *reinterpret_cast<__half2*>(p1)      = hp1;
                *reinterpret_cast<__half2*>(p1 + Nc) = lp1;
                *reinterpret_cast<__half2*>(p2)      = hp2;
                *reinterpret_cast<__half2*>(p2 + Nc) = lp2;
            }
        }
    }
}

// ---------------- GEMM kernel 2 (merged xl|xr): CTA 128x256, warp 64x64, 4-stage ----
#define BGSTAGE 4
#define BSTG_BYTES 49152
#define BGEMM_SMEM (BGSTAGE * BSTG_BYTES)

__global__ void __launch_bounds__(256, 1)
k_gemm_big(const __half* __restrict__ A, int lda, const __half* __restrict__ B,
           const float* __restrict__ bias, const float* __restrict__ bias2, int halfN,
           __half* __restrict__ C, int Ktot, int Nc) {
    extern __shared__ __align__(1024) char smem[];
    const uint32_t sb = smem_u32(smem);
    const int tid = threadIdx.x;
    const int lane = tid & 31, w = tid >> 5;
    const int wm = w & 1, wn = w >> 1;
    const int row0 = blockIdx.y * 128;
    const int col0 = blockIdx.x * 256;
    const int nch = Ktot >> 6;

    float acc[4][8][4];
    #pragma unroll
    for (int i = 0; i < 4; ++i)
        #pragma unroll
        for (int j = 0; j < 8; ++j)
            #pragma unroll
            for (int q = 0; q < 4; ++q) acc[i][j][q] = 0.f;

    uint32_t sm_offA[4], sm_offB[8];
    const __half* gA[4];
    const __half* gB[8];
    #pragma unroll
    for (int u = 0; u < 4; ++u) {
        int i = tid + u * 256;
        int r = i >> 3, seg = i & 7;
        uint32_t off = (uint32_t)(r * 128 + seg * 16);
        sm_offA[u] = off ^ ((off >> 3) & 0x70);
        gA[u] = A + (size_t)(row0 + r) * lda + (seg << 3);
    }
    #pragma unroll
    for (int u = 0; u < 8; ++u) {
        int i = tid + u * 256;
        int r = i >> 3, seg = i & 7;
        uint32_t off = (uint32_t)(r * 128 + seg * 16);
        sm_offB[u] = off ^ ((off >> 3) & 0x70);
        gB[u] = B + (size_t)(col0 + r) * Ktot + (seg << 3);
    }
    auto load_chunk = [&](int c) {
        const uint32_t s = sb + (uint32_t)((c % BGSTAGE) * BSTG_BYTES);
        const int kof = c << 6;
        #pragma unroll
        for (int u = 0; u < 4; ++u) cp16(s + sm_offA[u], gA[u] + kof);
        #pragma unroll
        for (int u = 0; u < 8; ++u) cp16(s + 16384 + sm_offB[u], gB[u] + kof);
        asm volatile("cp.async.commit_group;");
    };
    #pragma unroll
    for (int c = 0; c < BGSTAGE - 1; ++c) load_chunk(c);

    uint32_t a_base[4], a_swz[4];
    #pragma unroll
    for (int mb = 0; mb < 4; ++mb) {
        int row = wm * 64 + mb * 16 + (lane & 15);
        a_base[mb] = (uint32_t)(row * 128 + ((lane >> 4) << 4));
        a_swz[mb] = (uint32_t)((row & 7) << 4);
    }
    uint32_t b_base[4], b_swz[4];
    #pragma unroll
    for (int nb = 0; nb < 4; ++nb) {
        int row = wn * 64 + nb * 16 + (lane & 7) + ((lane >> 4) << 3);
        b_base[nb] = (uint32_t)(row * 128 + (((lane >> 3) & 1) << 4));
        b_swz[nb] = (uint32_t)((row & 7) << 4);
    }

    for (int c = 0; c < nch; ++c) {
        asm volatile("cp.async.wait_group %0;" :: "n"(BGSTAGE - 2));
        __syncthreads();
        if (c + BGSTAGE - 1 < nch) load_chunk(c + BGSTAGE - 1);
        else asm volatile("cp.async.commit_group;");
        const uint32_t stb = sb + (uint32_t)((c % BGSTAGE) * BSTG_BYTES);
        #pragma unroll
        for (int kk = 0; kk < 4; ++kk) {
            const uint32_t kby = (uint32_t)(kk * 32);
            uint32_t a[4][4];
            #pragma unroll
            for (int mb = 0; mb < 4; ++mb)
                ldsm_x4(a[mb], stb + ((a_base[mb] + kby) ^ a_swz[mb]));
            uint32_t b[4][4];
            #pragma unroll
            for (int nb = 0; nb < 4; ++nb)
                ldsm_x4(b[nb], stb + 16384 + ((b_base[nb] + kby) ^ b_swz[nb]));
            #pragma unroll
            for (int mb = 0; mb < 4; ++mb)
                #pragma unroll
                for (int nb = 0; nb < 4; ++nb) {
                    mma_f16(acc[mb][2 * nb],     a[mb], b[nb][0], b[nb][1]);
                    mma_f16(acc[mb][2 * nb + 1], a[mb], b[nb][2], b[nb][3]);
                }
        }
    }

    const float* bp = bias;
    int cadj = 0;
    if (bias2 && col0 >= halfN) { bp = bias2; cadj = halfN; }
    const int r_base = row0 + wm * 64 + (lane >> 2);
    const int c_base = col0 + wn * 64 + ((lane & 3) << 1);
    #pragma unroll
    for (int mb = 0; mb < 4; ++mb) {
        const int r1 = r_base + mb * 16;
        const int r2 = r1 + 8;
        #pragma unroll
        for (int nt = 0; nt < 8; ++nt) {
            const int col = c_base + nt * 8;
            float bx = bp[col - cadj], by = bp[col + 1 - cadj];
            __half2 t0 = __floats2half2_rn(acc[mb][nt][0] + bx, acc[mb][nt][1] + by);
            __half2 t1 = __floats2half2_rn(acc[mb][nt][2] + bx, acc[mb][nt][3] + by);
            *reinterpret_cast<__half2*>(&C[(size_t)r1 * Nc + col]) = t0;
            *reinterpret_cast<__half2*>(&C[(size_t)r2 * Nc + col]) = t1;
        }
    }
}

// ---------------- fused GATv2 edge kernel: registered att/xr/lee, spt metadata -------
#define EDGE_SMEM (6 * HDc * 4)

__global__ void __launch_bounds__(256, 4)
k_edge(const float* __restrict__ att_l, const float* __restrict__ bgat_l,
       int loff, __half* __restrict__ packH) {
    extern __shared__ float sm[];
    float* s_tab = sm;
    float* s_out = sm + 5 * HDc;

    const int tid = threadIdx.x;
    const int lane = tid & 31;
    const int base = ((tid >> 5) << 8) + (lane << 3);

    const float* tb = g_table + loff;
    #pragma unroll
    for (int u = 0; u < 40; ++u) s_tab[tid + u * 256] = tb[tid + u * 256];
    float att[8];
    {
        float4 a0 = *reinterpret_cast<const float4*>(att_l + base);
        float4 a1 = *reinterpret_cast<const float4*>(att_l + base + 4);
        att[0]=a0.x; att[1]=a0.y; att[2]=a0.z; att[3]=a0.w;
        att[4]=a1.x; att[5]=a1.y; att[6]=a1.z; att[7]=a1.w;
    }
    const float bg0 = bgat_l[tid];
    __syncthreads();

    for (int g = 0; g < EGc; ++g) {
        const int n = blockIdx.x * EGc + g;
        const int r0 = g_rowptr[n], r1 = g_rowptr[n + 1];
        const int deg = r1 - r0;
        const float inv = 1.0f / (float)(deg > 1 ? deg : 1);

        float c0 = (float)g_hist[n * NTc + 0];
        float c1 = (float)g_hist[n * NTc + 1];
        float c2 = (float)g_hist[n * NTc + 2];
        float c3 = (float)g_hist[n * NTc + 3];
        float c4 = (float)g_hist[n * NTc + 4];

        float xr[8];
        {
            uint4 raw = *reinterpret_cast<const uint4*>(g_xlr + (size_t)n * N2c + HDc + base);
            h8_to_f(raw, xr);
        }
        float lee[8];
        #pragma unroll
        for (int i = 0; i < 8; ++i) {
            float v = c0 * s_tab[0 * HDc + base + i];
            v = fmaf(c1, s_tab[1 * HDc + base + i], v);
            v = fmaf(c2, s_tab[2 * HDc + base + i], v);
            v = fmaf(c3, s_tab[3 * HDc + base + i], v);
            v = fmaf(c4, s_tab[4 * HDc + base + i], v);
            lee[i] = v * inv;
        }

        float m = -1e30f, d = 0.f;
        float acc[8];
        #pragma unroll
        for (int i = 0; i < 8; ++i) acc[i] = 0.f;

        auto fetch = [&](int idx, int& s, int& t) {
            if (idx < r1) { int pk = g_spt[idx]; s = pk >> 3; t = pk & 7; }
            else { s = n; t = -1; }
        };
        int s_c, t_c, s_n, t_n;
        fetch(r0, s_c, t_c);
        uint4 raw_c = *reinterpret_cast<const uint4*>(g_xlr + (size_t)s_c * N2c + base);
        fetch(r0 + 1, s_n, t_n);

        for (int idx = r0; idx <= r1; ++idx) {
            uint4 raw_n = *reinterpret_cast<const uint4*>(g_xlr + (size_t)s_n * N2c + base);
            int s_nn, t_nn;
            fetch(idx + 2, s_nn, t_nn);

            float xlv[8];
            h8_to_f(raw_c, xlv);
            float part = 0.f;
            if (t_c < 0) {
                #pragma unroll
                for (int i = 0; i < 8; ++i) {
                    float z = xlv[i] + xr[i] + lee[i];
                    z = z > 0.f ? z : 0.2f * z;
                    part = fmaf(z, att[i], part);
                }
            } else {
                const float* tab = s_tab + t_c * HDc + base;
                #pragma unroll
                for (int i = 0; i < 8; ++i) {
                    float z = xlv[i] + xr[i] + tab[i];
                    z = z > 0.f ? z : 0.2f * z;
                    part = fmaf(z, att[i], part);
                }
            }
            #pragma unroll
            for (int o = 16; o > 0; o >>= 1)
                part += __shfl_xor_sync(0xffffffffu, part, o);

            float mn = fmaxf(m, part);
            float sc = __expf(m - mn);
            float p  = __expf(part - mn);
            d = d * sc + p;
            #pragma unroll
            for (int i = 0; i < 8; ++i) acc[i] = fmaf(acc[i], sc, p * xlv[i]);
            m = mn;

            raw_c = raw_n; t_c = t_n;
            s_n = s_nn; t_n = t_nn;
        }

        float invd = 1.0f / d;
        #pragma unroll
        for (int i = 0; i < 8; ++i) s_out[base + i] = acc[i] * invd;
        __syncthreads();

        {
            int c = tid;
            float v = 0.f;
            #pragma unroll
            for (int h = 0; h < HHc; ++h) v += s_out[h * DHc + c];
            v = fmaf(v, 0.125f, bg0);
            v = fmaxf(v, 0.f);
            __half hi = __float2half_rn(v);
            __half lo = __float2half_rn(v - __half2float(hi));
            __half* p = packH + (size_t)n * (2 * DHc) + c;
            p[0]   = hi;
            p[DHc] = lo;
        }
        __syncthreads();
    }
}

// ---------------- host orchestration ----------------
extern "C" void kernel_launch(void* const* d_in, const int* in_sizes, int n_in,
                              void* d_out, int out_size) {
    const float* x         = (const float*)d_in[0];
    const int*   edge_index= (const int*)  d_in[1];
    const int*   edge_attr = (const int*)  d_in[2];
    const int*   node_types= (const int*)  d_in[3];
    const float* W_in      = (const float*)d_in[4];
    const float* b_in      = (const float*)d_in[5];
    const float* node_emb  = (const float*)d_in[6];
    const float* edge_emb  = (const float*)d_in[7];
    const float* Wl        = (const float*)d_in[8];
    const float* bl        = (const float*)d_in[9];
    const float* Wr        = (const float*)d_in[10];
    const float* br        = (const float*)d_in[11];
    const float* We        = (const float*)d_in[12];
    const float* att       = (const float*)d_in[13];
    const float* b_gat     = (const float*)d_in[14];
    const float* W_out     = (const float*)d_in[15];
    const float* b_out     = (const float*)d_in[16];
    float* out = (float*)d_out;

    __half* xlr;    cudaGetSymbolAddress((void**)&xlr, g_xlr);
    __half* Apk;    cudaGetSymbolAddress((void**)&Apk, g_Apack);
    __half* Hpk;    cudaGetSymbolAddress((void**)&Hpk, g_hpack);
    __half* Bpk;    cudaGetSymbolAddress((void**)&Bpk, g_Bpack);

    static cudaStream_t s2 = nullptr;
    static cudaEvent_t evFork = nullptr, evJoin = nullptr;
    if (!s2) {
        cudaStreamCreateWithFlags(&s2, cudaStreamNonBlocking);
        cudaEventCreateWithFlags(&evFork, cudaEventDisableTiming);
        cudaEventCreateWithFlags(&evJoin, cudaEventDisableTiming);
        cudaFuncSetAttribute(k_gemm_mma, cudaFuncAttributeMaxDynamicSharedMemorySize, GEMM_SMEM);
        cudaFuncSetAttribute(k_gemm_big, cudaFuncAttributeMaxDynamicSharedMemorySize, BGEMM_SMEM);
        cudaFuncSetAttribute(k_edge, cudaFuncAttributeMaxDynamicSharedMemorySize, EDGE_SMEM);
    }

    // fork: CSR build on side stream (independent of pack/proj/GEMM chain)
    cudaEventRecord(evFork, 0);
    cudaStreamWaitEvent(s2, evFork, 0);
    k_zero<<<(Nn * NTc + 255) / 256, 256, 0, s2>>>();
    k_count<<<(Ee + 255) / 256, 256, 0, s2>>>(edge_index, edge_attr);
    k_scan<<<1, 256, 0, s2>>>();
    k_fill<<<(Ee + 255) / 256, 256, 0, s2>>>(edge_index);
    k_sort<<<(Nn + 255) / 256, 256, 0, s2>>>(edge_index, edge_attr);
    cudaEventRecord(evJoin, s2);

    // main chain: pack -> in-proj -> merged GEMM L0
    k_pack_all<<<Nn + 256 + 3072 + 64 + 120, 256>>>(x, W_in, Wl, Wr, W_out,
                                                    edge_emb, We, Apk, Bpk);
    k_gemm_mma<<<dim3(2, 64), 256, GEMM_SMEM>>>(
        Apk, DINc, Bpk + OFF_WIN, b_in, nullptr, DINc, DHc, node_emb, node_types, Hpk);
    k_gemm_big<<<dim3(N2c / 256, Nn / 128), 256, BGEMM_SMEM>>>(
        Hpk, 2 * DHc, Bpk + OFF_WLR(0), bl, br, HDc, xlr, DHc, N2c);

    // join: CSR must be done before first edge kernel
    cudaStreamWaitEvent(0, evJoin, 0);

    for (int l = 0; l < LLc; ++l) {
        if (l > 0) {
            k_gemm_big<<<dim3(N2c / 256, Nn / 128), 256, BGEMM_SMEM>>>(
                Hpk, 2 * DHc, Bpk + OFF_WLR(l), bl + (size_t)l * HDc, br + (size_t)l * HDc,
                HDc, xlr, DHc, N2c);
        }
        k_edge<<<Nn / EGc, 256, EDGE_SMEM>>>(att + (size_t)l * HHc * DHc,
                                             b_gat + (size_t)l * DHc,
                                             l * NTc * HDc, Hpk);
    }

    // output projection -> d_out fp32
    k_gemm_mma<<<dim3(2, 64), 256, GEMM_SMEM>>>(
        Hpk, 2 * DHc, Bpk + OFF_WOUT, b_out, out, 2 * DHc, DHc, nullptr, nullptr, nullptr);

    (void)in_sizes; (void)n_in; (void)out_size;
}